// round 10
// baseline (speedup 1.0000x reference)
#include <cuda_runtime.h>
#include <cuda_bf16.h>

// Problem constants
#define TT    256
#define BB    1000
#define DD    300
#define H4    8
#define NCONS 8                 // consumer blocks (first 8 of grid)
#define NPROD (TT * 4)          // 1024 producer blocks, one per (t, quarter)

__device__ float g_xg[TT * BB * H4];   // xg[t][b][g]  (8.192 MB)
__device__ int   g_cnt[TT];            // quarters completed per timestep

// ---------------- helpers ----------------
__device__ __forceinline__ void fma2(unsigned long long& acc,
                                     unsigned long long a,
                                     unsigned long long b) {
    asm volatile("fma.rn.f32x2 %0, %1, %2, %3;" : "=l"(acc) : "l"(a), "l"(b), "l"(acc));
}
__device__ __forceinline__ unsigned long long pack2(float x) {
    unsigned long long r;
    asm("mov.b64 %0, {%1, %1};" : "=l"(r) : "r"(__float_as_uint(x)));
    return r;
}
__device__ __forceinline__ void unpack2(unsigned long long p, float& lo, float& hi) {
    unsigned a, b;
    asm("mov.b64 {%0, %1}, %2;" : "=r"(a), "=r"(b) : "l"(p));
    lo = __uint_as_float(a);
    hi = __uint_as_float(b);
}

__device__ __forceinline__ int ld_acquire(const int* p) {
    unsigned v;
    asm volatile("ld.acquire.gpu.global.u32 %0, [%1];" : "=r"(v) : "l"(p) : "memory");
    return (int)v;
}
__device__ __forceinline__ void wait_cnt(int t) {
    if (ld_acquire(&g_cnt[t]) >= 4) return;
    for (;;) {
        if (ld_acquire(&g_cnt[t]) >= 4) return;
        __nanosleep(64);
    }
}

// fast activations via MUFU.TANH (single-instruction tanh)
__device__ __forceinline__ float tanh_fast(float x) {
    float r;
    asm("tanh.approx.f32 %0, %1;" : "=f"(r) : "f"(x));
    return r;
}
__device__ __forceinline__ float sig_fast(float x) {
    return fmaf(tanh_fast(0.5f * x), 0.5f, 0.5f);
}

__global__ void reset_kernel() {
    g_cnt[threadIdx.x] = 0;
}

__global__ __launch_bounds__(256, 2) void fused_kernel(
    const float* __restrict__ x,      // [T,B,300]
    const float* __restrict__ Wih0,   // [8,300]
    const float* __restrict__ bih0,
    const float* __restrict__ bhh0,
    const float* __restrict__ h0in,   // [2,B,2]
    const float* __restrict__ c0in,
    const float* __restrict__ Whh0,   // [8,2]
    const float* __restrict__ Wih1,   // [8,2]
    const float* __restrict__ Whh1,   // [8,2]
    const float* __restrict__ bih1,
    const float* __restrict__ bhh1,
    const float* __restrict__ Wlin,   // [1,2]
    const float* __restrict__ blin,
    float* __restrict__ out)          // [B]
{
    __shared__ float sW[DD * H4];     // sW[d*8+g] = Wih0[g*300+d]
    __shared__ float sB[H4];

    const int bid = blockIdx.x;
    const int tid = threadIdx.x;

    if (bid >= NCONS) {
        // =================== PRODUCER (one block per (t, quarter)) ===========
        // (verbatim from R7 — the fastest producer measured in fused mode)
        const int pid = bid - NCONS;
        const int t   = pid >> 2;
        const int q   = pid & 3;

        for (int i = tid; i < DD * H4; i += 256) {
            int d = i >> 3, g = i & 7;
            sW[i] = Wih0[g * DD + d];
        }
        if (tid < H4) sB[tid] = bih0[tid] + bhh0[tid];
        __syncthreads();

        if (tid < 250) {
            const int row = t * BB + q * 250 + tid;
            const float4* xrow = reinterpret_cast<const float4*>(x + (size_t)row * DD);
            const ulonglong2* wp = reinterpret_cast<const ulonglong2*>(sW);

            ulonglong2 b01 = *reinterpret_cast<const ulonglong2*>(&sB[0]);
            ulonglong2 b23 = *reinterpret_cast<const ulonglong2*>(&sB[4]);
            unsigned long long a0 = b01.x, a1 = b01.y, a2 = b23.x, a3 = b23.y;

            #pragma unroll 5
            for (int d4 = 0; d4 < DD / 4; d4++) {
                float4 v = xrow[d4];
                #pragma unroll
                for (int j = 0; j < 4; j++) {
                    const float xs = (j == 0) ? v.x : (j == 1) ? v.y : (j == 2) ? v.z : v.w;
                    unsigned long long xp = pack2(xs);
                    ulonglong2 wA = wp[(d4 * 4 + j) * 2];
                    ulonglong2 wB = wp[(d4 * 4 + j) * 2 + 1];
                    fma2(a0, xp, wA.x);
                    fma2(a1, xp, wA.y);
                    fma2(a2, xp, wB.x);
                    fma2(a3, xp, wB.y);
                }
            }

            float4 o0, o1;
            unpack2(a0, o0.x, o0.y);
            unpack2(a1, o0.z, o0.w);
            unpack2(a2, o1.x, o1.y);
            unpack2(a3, o1.z, o1.w);
            float4* dst = reinterpret_cast<float4*>(&g_xg[(size_t)row * H4]);
            dst[0] = o0;
            dst[1] = o1;
        }
        __threadfence();
        __syncthreads();
        if (tid == 0) atomicAdd(&g_cnt[t], 1);
        return;
    }

    // =================== CONSUMER (blocks 0..7, 4 warps each) ================
    // Each warp: 32 elements. Lanes 0-15 run layer0 of elements (e, e+16);
    // lanes 16-31 run layer1 of the same pair, lagged one timestep.
    // 2 independent chains per lane -> 2x latency hiding.
    if (tid >= 128) return;
    const int warp = tid >> 5;
    const int lane = tid & 31;
    const bool l1  = (lane >= 16);
    const int gw   = bid * 4 + warp;          // 0..31
    const int e0   = gw * 32 + (lane & 15);   // element u=0
    const int e1   = e0 + 16;                 // element u=1
    const int b0   = (e0 < BB) ? e0 : (BB - 1);
    const int b1   = (e1 < BB) ? e1 : (BB - 1);

    float A0[H4], A1[H4], C0[H4], C1[H4], bb[H4];
    float ha[2], hb[2], ca[2], cb[2];
    float hpa[2] = {0.0f, 0.0f}, hpb[2] = {0.0f, 0.0f};
    float vb[2][H4];

    const int loff = l1 ? (BB * 2) : 0;
    if (!l1) {
        #pragma unroll
        for (int g = 0; g < H4; g++) {
            A0[g] = __ldg(&Whh0[g * 2 + 0]);
            A1[g] = __ldg(&Whh0[g * 2 + 1]);
            C0[g] = 0.0f; C1[g] = 0.0f; bb[g] = 0.0f;
        }
    } else {
        #pragma unroll
        for (int g = 0; g < H4; g++) {
            A0[g] = __ldg(&Whh1[g * 2 + 0]);
            A1[g] = __ldg(&Whh1[g * 2 + 1]);
            C0[g] = __ldg(&Wih1[g * 2 + 0]);
            C1[g] = __ldg(&Wih1[g * 2 + 1]);
            bb[g] = __ldg(&bih1[g]) + __ldg(&bhh1[g]);
        }
    }
    ha[0] = h0in[loff + b0 * 2 + 0]; hb[0] = h0in[loff + b0 * 2 + 1];
    ha[1] = h0in[loff + b1 * 2 + 0]; hb[1] = h0in[loff + b1 * 2 + 1];
    ca[0] = c0in[loff + b0 * 2 + 0]; cb[0] = c0in[loff + b0 * 2 + 1];
    ca[1] = c0in[loff + b1 * 2 + 0]; cb[1] = c0in[loff + b1 * 2 + 1];

    #pragma unroll
    for (int u = 0; u < 2; u++)
        #pragma unroll
        for (int g = 0; g < H4; g++)
            vb[u][g] = bb[g];

    const float wl0 = __ldg(&Wlin[0]), wl1 = __ldg(&Wlin[1]), bl = __ldg(&blin[0]);

    const float4* xg4 = reinterpret_cast<const float4*>(g_xg);
    const int ib0 = b0 * 2, ib1 = b1 * 2;

    wait_cnt(0);
    if (!l1) {
        float4 v00 = xg4[ib0],     v01 = xg4[ib0 + 1];
        float4 v10 = xg4[ib1],     v11 = xg4[ib1 + 1];
        vb[0][0] = v00.x; vb[0][1] = v00.y; vb[0][2] = v00.z; vb[0][3] = v00.w;
        vb[0][4] = v01.x; vb[0][5] = v01.y; vb[0][6] = v01.z; vb[0][7] = v01.w;
        vb[1][0] = v10.x; vb[1][1] = v10.y; vb[1][2] = v10.z; vb[1][3] = v10.w;
        vb[1][4] = v11.x; vb[1][5] = v11.y; vb[1][6] = v11.z; vb[1][7] = v11.w;
    }

    for (int s = 0; s <= TT; s++) {
        float4 n00, n01, n10, n11;
        const bool pf = (s + 1 < TT);
        if (pf) {
            wait_cnt(s + 1);
            if (!l1) {
                const int tb = (s + 1) * (BB * 2);
                n00 = xg4[tb + ib0];     n01 = xg4[tb + ib0 + 1];
                n10 = xg4[tb + ib1];     n11 = xg4[tb + ib1 + 1];
            }
        }

        const bool valid = l1 ? (s >= 1) : (s < TT);

        #pragma unroll
        for (int u = 0; u < 2; u++) {
            float pre[H4];
            #pragma unroll
            for (int g = 0; g < H4; g++)
                pre[g] = fmaf(C0[g], hpa[u], fmaf(C1[g], hpb[u], vb[u][g]));
            #pragma unroll
            for (int g = 0; g < H4; g++)
                pre[g] = fmaf(A0[g], ha[u], fmaf(A1[g], hb[u], pre[g]));

            float i0 = sig_fast(pre[0]),  i1 = sig_fast(pre[1]);
            float f0 = sig_fast(pre[2]),  f1 = sig_fast(pre[3]);
            float g0 = tanh_fast(pre[4]), g1 = tanh_fast(pre[5]);
            float o0 = sig_fast(pre[6]),  o1 = sig_fast(pre[7]);
            float nca = fmaf(f0, ca[u], i0 * g0);
            float ncb = fmaf(f1, cb[u], i1 * g1);
            float nha = o0 * tanh_fast(nca);
            float nhb = o1 * tanh_fast(ncb);

            if (valid) { ca[u] = nca; cb[u] = ncb; ha[u] = nha; hb[u] = nhb; }
        }

        hpa[0] = __shfl_up_sync(0xffffffffu, ha[0], 16);
        hpb[0] = __shfl_up_sync(0xffffffffu, hb[0], 16);
        hpa[1] = __shfl_up_sync(0xffffffffu, ha[1], 16);
        hpb[1] = __shfl_up_sync(0xffffffffu, hb[1], 16);

        if (pf && !l1) {
            vb[0][0] = n00.x; vb[0][1] = n00.y; vb[0][2] = n00.z; vb[0][3] = n00.w;
            vb[0][4] = n01.x; vb[0][5] = n01.y; vb[0][6] = n01.z; vb[0][7] = n01.w;
            vb[1][0] = n10.x; vb[1][1] = n10.y; vb[1][2] = n10.z; vb[1][3] = n10.w;
            vb[1][4] = n11.x; vb[1][5] = n11.y; vb[1][6] = n11.z; vb[1][7] = n11.w;
        }
    }

    if (l1) {
        if (e0 < BB) out[b0] = fmaf(wl0, ha[0], fmaf(wl1, hb[0], bl));
        if (e1 < BB) out[b1] = fmaf(wl0, ha[1], fmaf(wl1, hb[1], bl));
    }
}

// ---------------------------------------------------------------------------
extern "C" void kernel_launch(void* const* d_in, const int* in_sizes, int n_in,
                              void* d_out, int out_size)
{
    const float* x     = (const float*)d_in[0];
    const float* h0    = (const float*)d_in[1];
    const float* c0    = (const float*)d_in[2];
    const float* Wih0  = (const float*)d_in[3];
    const float* Whh0  = (const float*)d_in[4];
    const float* bih0  = (const float*)d_in[5];
    const float* bhh0  = (const float*)d_in[6];
    const float* Wih1  = (const float*)d_in[7];
    const float* Whh1  = (const float*)d_in[8];
    const float* bih1  = (const float*)d_in[9];
    const float* bhh1  = (const float*)d_in[10];
    const float* Wlin  = (const float*)d_in[11];
    const float* blin  = (const float*)d_in[12];
    float* out = (float*)d_out;

    reset_kernel<<<1, TT>>>();
    fused_kernel<<<NCONS + NPROD, 256>>>(
        x, Wih0, bih0, bhh0,
        h0, c0, Whh0, Wih1, Whh1, bih1, bhh1, Wlin, blin,
        out);
}

// round 11
// speedup vs baseline: 1.9495x; 1.9495x over previous
#include <cuda_runtime.h>
#include <cuda_bf16.h>

// Problem constants
#define TT    256
#define BB    1000
#define DD    300
#define H4    8
#define ROWS_PER_BLK 256
#define NBLK_GEMM   (TT * BB / ROWS_PER_BLK)   // 1000

// padded W smem: per d4-group (4 d x 8 g = 32 floats) in 36-float slot
#define WSLOT 36
#define WP_FLOATS (75 * WSLOT)   // 2700

__device__ float g_xg[TT * BB * H4];   // xg[t][b][g]  (8.192 MB)

// ---------------- helpers ----------------
__device__ __forceinline__ void fma2(unsigned long long& acc,
                                     unsigned long long a,
                                     unsigned long long b) {
    asm volatile("fma.rn.f32x2 %0, %1, %2, %3;" : "=l"(acc) : "l"(a), "l"(b), "l"(acc));
}
__device__ __forceinline__ unsigned long long add2(unsigned long long a,
                                                   unsigned long long b) {
    unsigned long long r;
    asm("add.rn.f32x2 %0, %1, %2;" : "=l"(r) : "l"(a), "l"(b));
    return r;
}
__device__ __forceinline__ unsigned long long pack2(float x) {
    unsigned long long r;
    asm("mov.b64 %0, {%1, %1};" : "=l"(r) : "r"(__float_as_uint(x)));
    return r;
}
__device__ __forceinline__ void unpack2(unsigned long long p, float& lo, float& hi) {
    unsigned a, b;
    asm("mov.b64 {%0, %1}, %2;" : "=r"(a), "=r"(b) : "l"(p));
    lo = __uint_as_float(a);
    hi = __uint_as_float(b);
}

// fast activations via MUFU.TANH (validated: rel_err ~1e-7 in R10)
__device__ __forceinline__ float tanh_fast(float x) {
    float r;
    asm("tanh.approx.f32 %0, %1;" : "=f"(r) : "f"(x));
    return r;
}
__device__ __forceinline__ float sig_fast(float x) {
    return fmaf(tanh_fast(0.5f * x), 0.5f, 0.5f);
}

// ===========================================================================
// Kernel 1: xg = x @ Wih0^T + (b_ih0 + b_hh0)   [R9 verbatim, 101us measured]
// ===========================================================================
__global__ __launch_bounds__(256) void gemm_kernel(
    const float* __restrict__ x,      // [T*B, 300]
    const float* __restrict__ Wih0,   // [8, 300]
    const float* __restrict__ bih0,
    const float* __restrict__ bhh0)
{
    __shared__ float sWp[WP_FLOATS];  // sWp[d4*36 + j*8 + g]
    __shared__ float sB[H4];

    const int bid = blockIdx.x;
    const int tid = threadIdx.x;

    for (int i = tid; i < 75 * 32; i += 256) {
        int d4  = i >> 5;
        int rem = i & 31;
        int j   = rem >> 3, g = rem & 7;
        sWp[d4 * WSLOT + j * 8 + g] = Wih0[g * DD + d4 * 4 + j];
    }
    if (tid < H4) sB[tid] = bih0[tid] + bhh0[tid];
    __syncthreads();

    const int warp = tid >> 5;
    const int lane = tid & 31;
    const int r8   = lane >> 2;
    const int c    = lane & 3;
    const int wbase = bid * ROWS_PER_BLK + warp * 32;

    ulonglong2 b01 = *reinterpret_cast<const ulonglong2*>(&sB[0]);
    ulonglong2 b23 = *reinterpret_cast<const ulonglong2*>(&sB[4]);

    #pragma unroll
    for (int jj = 0; jj < 4; jj++) {
        const int row = wbase + jj * 8 + r8;
        const float4* xrow = reinterpret_cast<const float4*>(x + (size_t)row * DD);

        unsigned long long a0 = 0, a1 = 0, a2 = 0, a3 = 0;

        #pragma unroll
        for (int i = 0; i < 19; i++) {
            const int d4 = i * 4 + c;
            if (d4 < 75) {
                float4 v = xrow[d4];
                const float* wb = &sWp[d4 * WSLOT];
                #pragma unroll
                for (int j = 0; j < 4; j++) {
                    const float xs = (j == 0) ? v.x : (j == 1) ? v.y : (j == 2) ? v.z : v.w;
                    unsigned long long xp = pack2(xs);
                    ulonglong2 wA = *reinterpret_cast<const ulonglong2*>(wb + j * 8);
                    ulonglong2 wB = *reinterpret_cast<const ulonglong2*>(wb + j * 8 + 4);
                    fma2(a0, xp, wA.x);
                    fma2(a1, xp, wA.y);
                    fma2(a2, xp, wB.x);
                    fma2(a3, xp, wB.y);
                }
            }
        }

        a0 = add2(a0, __shfl_xor_sync(0xffffffffu, a0, 1));
        a1 = add2(a1, __shfl_xor_sync(0xffffffffu, a1, 1));
        a2 = add2(a2, __shfl_xor_sync(0xffffffffu, a2, 1));
        a3 = add2(a3, __shfl_xor_sync(0xffffffffu, a3, 1));
        a0 = add2(a0, __shfl_xor_sync(0xffffffffu, a0, 2));
        a1 = add2(a1, __shfl_xor_sync(0xffffffffu, a1, 2));
        a2 = add2(a2, __shfl_xor_sync(0xffffffffu, a2, 2));
        a3 = add2(a3, __shfl_xor_sync(0xffffffffu, a3, 2));

        if (c == 0) {
            a0 = add2(a0, b01.x);
            a1 = add2(a1, b01.y);
            a2 = add2(a2, b23.x);
            a3 = add2(a3, b23.y);
            float4 o0, o1;
            unpack2(a0, o0.x, o0.y);
            unpack2(a1, o0.z, o0.w);
            unpack2(a2, o1.x, o1.y);
            unpack2(a3, o1.z, o1.w);
            float4* dst = reinterpret_cast<float4*>(&g_xg[(size_t)row * H4]);
            dst[0] = o0;
            dst[1] = o1;
        }
    }
}

// ===========================================================================
// Kernel 2: 2-layer LSTM recurrence + final linear.
// 64 blocks x 32 threads -> one warp per SM.
// Lanes 0-15: layer0 of 16 elements; lanes 16-31: layer1, lagged one step.
// NEW: 4-deep register prefetch ring hides xg load latency; tanh.approx.
// ===========================================================================
__global__ __launch_bounds__(32) void recur_kernel(
    const float* __restrict__ h0in,  // [2,B,2]
    const float* __restrict__ c0in,
    const float* __restrict__ Whh0,  // [8,2]
    const float* __restrict__ Wih1,  // [8,2]
    const float* __restrict__ Whh1,  // [8,2]
    const float* __restrict__ bih1,
    const float* __restrict__ bhh1,
    const float* __restrict__ Wlin,  // [1,2]
    const float* __restrict__ blin,
    float* __restrict__ out)         // [B]
{
    const int lane = threadIdx.x;
    const bool l1  = (lane >= 16);
    const int e    = blockIdx.x * 16 + (lane & 15);   // 0..1023
    const int b    = (e < BB) ? e : (BB - 1);

    float A0[H4], A1[H4], C0[H4], C1[H4], bb[H4];
    float ha, hb, ca, cb;
    float hpa = 0.0f, hpb = 0.0f;

    if (!l1) {
        #pragma unroll
        for (int g = 0; g < H4; g++) {
            A0[g] = __ldg(&Whh0[g * 2 + 0]);
            A1[g] = __ldg(&Whh0[g * 2 + 1]);
            C0[g] = 0.0f; C1[g] = 0.0f; bb[g] = 0.0f;
        }
        ha = h0in[b * 2 + 0]; hb = h0in[b * 2 + 1];
        ca = c0in[b * 2 + 0]; cb = c0in[b * 2 + 1];
    } else {
        #pragma unroll
        for (int g = 0; g < H4; g++) {
            A0[g] = __ldg(&Whh1[g * 2 + 0]);
            A1[g] = __ldg(&Whh1[g * 2 + 1]);
            C0[g] = __ldg(&Wih1[g * 2 + 0]);
            C1[g] = __ldg(&Wih1[g * 2 + 1]);
            bb[g] = __ldg(&bih1[g]) + __ldg(&bhh1[g]);
        }
        ha = h0in[BB * 2 + b * 2 + 0]; hb = h0in[BB * 2 + b * 2 + 1];
        ca = c0in[BB * 2 + b * 2 + 0]; cb = c0in[BB * 2 + b * 2 + 1];
    }
    const float wl0 = __ldg(&Wlin[0]), wl1 = __ldg(&Wlin[1]), bl = __ldg(&blin[0]);

    const float4* xg4 = reinterpret_cast<const float4*>(g_xg);
    const int idx0 = b * 2;
    const int ST   = BB * 2;   // float4 stride per timestep

    // ---- prefetch ring: slots for steps s, s+1, s+2, s+3 ----
    float4 r0[4], r1[4];
    if (!l1) {
        #pragma unroll
        for (int d = 0; d < 4; d++) {
            r0[d] = __ldg(&xg4[idx0 + d * ST]);
            r1[d] = __ldg(&xg4[idx0 + d * ST + 1]);
        }
    }

    float vb[H4];
    #pragma unroll
    for (int g = 0; g < H4; g++) vb[g] = bb[g];   // l1 lanes keep this forever

    #pragma unroll 1
    for (int s4 = 0; s4 < TT / 4; s4++) {
        #pragma unroll
        for (int u = 0; u < 4; u++) {
            const int s = s4 * 4 + u;

            // consume slot u (l0 lanes only)
            if (!l1) {
                vb[0] = r0[u].x; vb[1] = r0[u].y; vb[2] = r0[u].z; vb[3] = r0[u].w;
                vb[4] = r1[u].x; vb[5] = r1[u].y; vb[6] = r1[u].z; vb[7] = r1[u].w;
            }
            // refill slot u with step s+4 (issued early; consumed 4 steps later)
            if (!l1 && s + 4 < TT) {
                r0[u] = __ldg(&xg4[idx0 + (s + 4) * ST]);
                r1[u] = __ldg(&xg4[idx0 + (s + 4) * ST + 1]);
            }

            float pre[H4];
            #pragma unroll
            for (int g = 0; g < H4; g++)
                pre[g] = fmaf(C0[g], hpa, fmaf(C1[g], hpb, vb[g]));
            #pragma unroll
            for (int g = 0; g < H4; g++)
                pre[g] = fmaf(A0[g], ha, fmaf(A1[g], hb, pre[g]));

            float i0 = sig_fast(pre[0]),  i1 = sig_fast(pre[1]);
            float f0 = sig_fast(pre[2]),  f1 = sig_fast(pre[3]);
            float g0 = tanh_fast(pre[4]), g1 = tanh_fast(pre[5]);
            float o0 = sig_fast(pre[6]),  o1 = sig_fast(pre[7]);
            float nca = fmaf(f0, ca, i0 * g0);
            float ncb = fmaf(f1, cb, i1 * g1);
            float nha = o0 * tanh_fast(nca);
            float nhb = o1 * tanh_fast(ncb);

            // l0 always valid in main loop; l1 valid from s>=1
            const bool valid = l1 ? (s >= 1) : true;
            if (valid) { ca = nca; cb = ncb; ha = nha; hb = nhb; }

            hpa = __shfl_up_sync(0xffffffffu, ha, 16);
            hpb = __shfl_up_sync(0xffffffffu, hb, 16);
        }
    }

    // epilogue step s = TT: layer-1 lanes process t = TT-1 (uses last handoff)
    {
        float pre[H4];
        #pragma unroll
        for (int g = 0; g < H4; g++)
            pre[g] = fmaf(C0[g], hpa, fmaf(C1[g], hpb, bb[g]));
        #pragma unroll
        for (int g = 0; g < H4; g++)
            pre[g] = fmaf(A0[g], ha, fmaf(A1[g], hb, pre[g]));

        float i0 = sig_fast(pre[0]),  i1 = sig_fast(pre[1]);
        float f0 = sig_fast(pre[2]),  f1 = sig_fast(pre[3]);
        float g0 = tanh_fast(pre[4]), g1 = tanh_fast(pre[5]);
        float o0 = sig_fast(pre[6]),  o1 = sig_fast(pre[7]);
        float nca = fmaf(f0, ca, i0 * g0);
        float ncb = fmaf(f1, cb, i1 * g1);
        float nha = o0 * tanh_fast(nca);
        float nhb = o1 * tanh_fast(ncb);

        if (l1) { ca = nca; cb = ncb; ha = nha; hb = nhb; }
    }

    if (l1 && e < BB)
        out[b] = fmaf(wl0, ha, fmaf(wl1, hb, bl));
}

// ---------------------------------------------------------------------------
extern "C" void kernel_launch(void* const* d_in, const int* in_sizes, int n_in,
                              void* d_out, int out_size)
{
    const float* x     = (const float*)d_in[0];
    const float* h0    = (const float*)d_in[1];
    const float* c0    = (const float*)d_in[2];
    const float* Wih0  = (const float*)d_in[3];
    const float* Whh0  = (const float*)d_in[4];
    const float* bih0  = (const float*)d_in[5];
    const float* bhh0  = (const float*)d_in[6];
    const float* Wih1  = (const float*)d_in[7];
    const float* Whh1  = (const float*)d_in[8];
    const float* bih1  = (const float*)d_in[9];
    const float* bhh1  = (const float*)d_in[10];
    const float* Wlin  = (const float*)d_in[11];
    const float* blin  = (const float*)d_in[12];
    float* out = (float*)d_out;

    gemm_kernel<<<NBLK_GEMM, 256>>>(x, Wih0, bih0, bhh0);
    recur_kernel<<<64, 32>>>(h0, c0, Whh0, Wih1, Whh1, bih1, bhh1, Wlin, blin, out);
}

// round 12
// speedup vs baseline: 2.0759x; 1.0648x over previous
#include <cuda_runtime.h>
#include <cuda_bf16.h>

// Problem constants
#define TT    256
#define BB    1000
#define DD    300
#define H4    8
#define NCONS 8                 // consumer blocks (first 8 of grid)
#define NPROD (TT * 4)          // 1024 producer blocks, one per (t, quarter)

__device__ float g_xg[TT * BB * H4];   // xg[t][b][g]  (8.192 MB)
__device__ int   g_cnt[TT];            // quarters completed per timestep

// ---------------- helpers ----------------
__device__ __forceinline__ void fma2(unsigned long long& acc,
                                     unsigned long long a,
                                     unsigned long long b) {
    asm volatile("fma.rn.f32x2 %0, %1, %2, %3;" : "=l"(acc) : "l"(a), "l"(b), "l"(acc));
}
__device__ __forceinline__ unsigned long long pack2(float x) {
    unsigned long long r;
    asm("mov.b64 %0, {%1, %1};" : "=l"(r) : "r"(__float_as_uint(x)));
    return r;
}
__device__ __forceinline__ void unpack2(unsigned long long p, float& lo, float& hi) {
    unsigned a, b;
    asm("mov.b64 {%0, %1}, %2;" : "=r"(a), "=r"(b) : "l"(p));
    lo = __uint_as_float(a);
    hi = __uint_as_float(b);
}

__device__ __forceinline__ int ld_acquire(const int* p) {
    unsigned v;
    asm volatile("ld.acquire.gpu.global.u32 %0, [%1];" : "=r"(v) : "l"(p) : "memory");
    return (int)v;
}
__device__ __forceinline__ void wait_cnt(int t) {
    if (ld_acquire(&g_cnt[t]) >= 4) return;
    for (;;) {
        if (ld_acquire(&g_cnt[t]) >= 4) return;
        __nanosleep(64);
    }
}

// fast activations via MUFU.TANH (validated: rel_err ~1e-7 in R10/R11)
__device__ __forceinline__ float tanh_fast(float x) {
    float r;
    asm("tanh.approx.f32 %0, %1;" : "=f"(r) : "f"(x));
    return r;
}
__device__ __forceinline__ float sig_fast(float x) {
    return fmaf(tanh_fast(0.5f * x), 0.5f, 0.5f);
}

__global__ void reset_kernel() {
    g_cnt[threadIdx.x] = 0;
}

__global__ __launch_bounds__(256, 2) void fused_kernel(
    const float* __restrict__ x,      // [T,B,300]
    const float* __restrict__ Wih0,   // [8,300]
    const float* __restrict__ bih0,
    const float* __restrict__ bhh0,
    const float* __restrict__ h0in,   // [2,B,2]
    const float* __restrict__ c0in,
    const float* __restrict__ Whh0,   // [8,2]
    const float* __restrict__ Wih1,   // [8,2]
    const float* __restrict__ Whh1,   // [8,2]
    const float* __restrict__ bih1,
    const float* __restrict__ bhh1,
    const float* __restrict__ Wlin,   // [1,2]
    const float* __restrict__ blin,
    float* __restrict__ out)          // [B]
{
    __shared__ float sW[DD * H4];     // sW[d*8+g] = Wih0[g*300+d]
    __shared__ float sB[H4];

    const int bid = blockIdx.x;
    const int tid = threadIdx.x;

    if (bid >= NCONS) {
        // =================== PRODUCER (R7 verbatim) ==========================
        const int pid = bid - NCONS;
        const int t   = pid >> 2;
        const int q   = pid & 3;

        for (int i = tid; i < DD * H4; i += 256) {
            int d = i >> 3, g = i & 7;
            sW[i] = Wih0[g * DD + d];
        }
        if (tid < H4) sB[tid] = bih0[tid] + bhh0[tid];
        __syncthreads();

        if (tid < 250) {
            const int row = t * BB + q * 250 + tid;
            const float4* xrow = reinterpret_cast<const float4*>(x + (size_t)row * DD);
            const ulonglong2* wp = reinterpret_cast<const ulonglong2*>(sW);

            ulonglong2 b01 = *reinterpret_cast<const ulonglong2*>(&sB[0]);
            ulonglong2 b23 = *reinterpret_cast<const ulonglong2*>(&sB[4]);
            unsigned long long a0 = b01.x, a1 = b01.y, a2 = b23.x, a3 = b23.y;

            #pragma unroll 5
            for (int d4 = 0; d4 < DD / 4; d4++) {
                float4 v = xrow[d4];
                #pragma unroll
                for (int j = 0; j < 4; j++) {
                    const float xs = (j == 0) ? v.x : (j == 1) ? v.y : (j == 2) ? v.z : v.w;
                    unsigned long long xp = pack2(xs);
                    ulonglong2 wA = wp[(d4 * 4 + j) * 2];
                    ulonglong2 wB = wp[(d4 * 4 + j) * 2 + 1];
                    fma2(a0, xp, wA.x);
                    fma2(a1, xp, wA.y);
                    fma2(a2, xp, wB.x);
                    fma2(a3, xp, wB.y);
                }
            }

            float4 o0, o1;
            unpack2(a0, o0.x, o0.y);
            unpack2(a1, o0.z, o0.w);
            unpack2(a2, o1.x, o1.y);
            unpack2(a3, o1.z, o1.w);
            float4* dst = reinterpret_cast<float4*>(&g_xg[(size_t)row * H4]);
            dst[0] = o0;
            dst[1] = o1;
        }
        __threadfence();
        __syncthreads();
        if (tid == 0) atomicAdd(&g_cnt[t], 1);
        return;
    }

    // =================== CONSUMER (R11 ring consumer, 8 blocks x 8 warps) ====
    const int warp = tid >> 5;
    const int lane = tid & 31;
    const bool l1  = (lane >= 16);
    const int e    = (bid * 8 + warp) * 16 + (lane & 15);   // 0..1023
    const int b    = (e < BB) ? e : (BB - 1);

    float A0[H4], A1[H4], C0[H4], C1[H4], bb[H4];
    float ha, hb, ca, cb;
    float hpa = 0.0f, hpb = 0.0f;

    if (!l1) {
        #pragma unroll
        for (int g = 0; g < H4; g++) {
            A0[g] = __ldg(&Whh0[g * 2 + 0]);
            A1[g] = __ldg(&Whh0[g * 2 + 1]);
            C0[g] = 0.0f; C1[g] = 0.0f; bb[g] = 0.0f;
        }
        ha = h0in[b * 2 + 0]; hb = h0in[b * 2 + 1];
        ca = c0in[b * 2 + 0]; cb = c0in[b * 2 + 1];
    } else {
        #pragma unroll
        for (int g = 0; g < H4; g++) {
            A0[g] = __ldg(&Whh1[g * 2 + 0]);
            A1[g] = __ldg(&Whh1[g * 2 + 1]);
            C0[g] = __ldg(&Wih1[g * 2 + 0]);
            C1[g] = __ldg(&Wih1[g * 2 + 1]);
            bb[g] = __ldg(&bih1[g]) + __ldg(&bhh1[g]);
        }
        ha = h0in[BB * 2 + b * 2 + 0]; hb = h0in[BB * 2 + b * 2 + 1];
        ca = c0in[BB * 2 + b * 2 + 0]; cb = c0in[BB * 2 + b * 2 + 1];
    }
    const float wl0 = __ldg(&Wlin[0]), wl1 = __ldg(&Wlin[1]), bl = __ldg(&blin[0]);

    const float4* xg4 = reinterpret_cast<const float4*>(g_xg);
    const int idx0 = b * 2;
    const int ST   = BB * 2;   // float4 stride per timestep

    // ---- prefetch ring: slots for steps s..s+3 (flag-gated) ----
    float4 r0[4], r1[4];
    #pragma unroll
    for (int d = 0; d < 4; d++) {
        wait_cnt(d);
        if (!l1) {
            r0[d] = __ldg(&xg4[idx0 + d * ST]);
            r1[d] = __ldg(&xg4[idx0 + d * ST + 1]);
        }
    }

    float vb[H4];
    #pragma unroll
    for (int g = 0; g < H4; g++) vb[g] = bb[g];   // l1 lanes keep this forever

    #pragma unroll 1
    for (int s4 = 0; s4 < TT / 4; s4++) {
        #pragma unroll
        for (int u = 0; u < 4; u++) {
            const int s = s4 * 4 + u;

            // consume slot u (l0 lanes only)
            if (!l1) {
                vb[0] = r0[u].x; vb[1] = r0[u].y; vb[2] = r0[u].z; vb[3] = r0[u].w;
                vb[4] = r1[u].x; vb[5] = r1[u].y; vb[6] = r1[u].z; vb[7] = r1[u].w;
            }
            // refill slot u with step s+4 (flag-gated; consumed 4 steps later)
            if (s + 4 < TT) {
                wait_cnt(s + 4);
                if (!l1) {
                    r0[u] = __ldg(&xg4[idx0 + (s + 4) * ST]);
                    r1[u] = __ldg(&xg4[idx0 + (s + 4) * ST + 1]);
                }
            }

            float pre[H4];
            #pragma unroll
            for (int g = 0; g < H4; g++)
                pre[g] = fmaf(C0[g], hpa, fmaf(C1[g], hpb, vb[g]));
            #pragma unroll
            for (int g = 0; g < H4; g++)
                pre[g] = fmaf(A0[g], ha, fmaf(A1[g], hb, pre[g]));

            float i0 = sig_fast(pre[0]),  i1 = sig_fast(pre[1]);
            float f0 = sig_fast(pre[2]),  f1 = sig_fast(pre[3]);
            float g0 = tanh_fast(pre[4]), g1 = tanh_fast(pre[5]);
            float o0 = sig_fast(pre[6]),  o1 = sig_fast(pre[7]);
            float nca = fmaf(f0, ca, i0 * g0);
            float ncb = fmaf(f1, cb, i1 * g1);
            float nha = o0 * tanh_fast(nca);
            float nhb = o1 * tanh_fast(ncb);

            const bool valid = l1 ? (s >= 1) : true;
            if (valid) { ca = nca; cb = ncb; ha = nha; hb = nhb; }

            hpa = __shfl_up_sync(0xffffffffu, ha, 16);
            hpb = __shfl_up_sync(0xffffffffu, hb, 16);
        }
    }

    // epilogue step s = TT: layer-1 lanes process t = TT-1
    {
        float pre[H4];
        #pragma unroll
        for (int g = 0; g < H4; g++)
            pre[g] = fmaf(C0[g], hpa, fmaf(C1[g], hpb, bb[g]));
        #pragma unroll
        for (int g = 0; g < H4; g++)
            pre[g] = fmaf(A0[g], ha, fmaf(A1[g], hb, pre[g]));

        float i0 = sig_fast(pre[0]),  i1 = sig_fast(pre[1]);
        float f0 = sig_fast(pre[2]),  f1 = sig_fast(pre[3]);
        float g0 = tanh_fast(pre[4]), g1 = tanh_fast(pre[5]);
        float o0 = sig_fast(pre[6]),  o1 = sig_fast(pre[7]);
        float nca = fmaf(f0, ca, i0 * g0);
        float ncb = fmaf(f1, cb, i1 * g1);
        float nha = o0 * tanh_fast(nca);
        float nhb = o1 * tanh_fast(ncb);

        if (l1) { ca = nca; cb = ncb; ha = nha; hb = nhb; }
    }

    if (l1 && e < BB)
        out[b] = fmaf(wl0, ha, fmaf(wl1, hb, bl));
}

// ---------------------------------------------------------------------------
extern "C" void kernel_launch(void* const* d_in, const int* in_sizes, int n_in,
                              void* d_out, int out_size)
{
    const float* x     = (const float*)d_in[0];
    const float* h0    = (const float*)d_in[1];
    const float* c0    = (const float*)d_in[2];
    const float* Wih0  = (const float*)d_in[3];
    const float* Whh0  = (const float*)d_in[4];
    const float* bih0  = (const float*)d_in[5];
    const float* bhh0  = (const float*)d_in[6];
    const float* Wih1  = (const float*)d_in[7];
    const float* Whh1  = (const float*)d_in[8];
    const float* bih1  = (const float*)d_in[9];
    const float* bhh1  = (const float*)d_in[10];
    const float* Wlin  = (const float*)d_in[11];
    const float* blin  = (const float*)d_in[12];
    float* out = (float*)d_out;

    reset_kernel<<<1, TT>>>();
    fused_kernel<<<NCONS + NPROD, 256>>>(
        x, Wih0, bih0, bhh0,
        h0, c0, Whh0, Wih1, Whh1, bih1, bhh1, Wlin, blin,
        out);
}

// round 13
// speedup vs baseline: 2.1929x; 1.0563x over previous
#include <cuda_runtime.h>
#include <cuda_bf16.h>

// Problem constants
#define TT    256
#define BB    1000
#define DD    300
#define H4    8
#define NCONS 8                   // consumer blocks (first 8 of grid)
#define TROWS 64                  // rows per producer tile
#define NT_PER_T 16               // tiles per timestep
#define NPROD (TT * NT_PER_T)     // 4096 producer blocks

// padded W smem: per d4-group (4 d x 8 g = 32 floats) in 36-float slot
#define WSLOT 36
#define WP_FLOATS (75 * WSLOT)    // 2700

__device__ float g_xg[TT * BB * H4];   // xg[t][b][g]  (8.192 MB)
__device__ int   g_cnt[TT];            // tiles completed per timestep

// ---------------- helpers ----------------
__device__ __forceinline__ void fma2(unsigned long long& acc,
                                     unsigned long long a,
                                     unsigned long long b) {
    asm volatile("fma.rn.f32x2 %0, %1, %2, %3;" : "=l"(acc) : "l"(a), "l"(b), "l"(acc));
}
__device__ __forceinline__ unsigned long long add2(unsigned long long a,
                                                   unsigned long long b) {
    unsigned long long r;
    asm("add.rn.f32x2 %0, %1, %2;" : "=l"(r) : "l"(a), "l"(b));
    return r;
}
__device__ __forceinline__ unsigned long long pack2(float x) {
    unsigned long long r;
    asm("mov.b64 %0, {%1, %1};" : "=l"(r) : "r"(__float_as_uint(x)));
    return r;
}
__device__ __forceinline__ void unpack2(unsigned long long p, float& lo, float& hi) {
    unsigned a, b;
    asm("mov.b64 {%0, %1}, %2;" : "=r"(a), "=r"(b) : "l"(p));
    lo = __uint_as_float(a);
    hi = __uint_as_float(b);
}

__device__ __forceinline__ int ld_acquire(const int* p) {
    unsigned v;
    asm volatile("ld.acquire.gpu.global.u32 %0, [%1];" : "=r"(v) : "l"(p) : "memory");
    return (int)v;
}
__device__ __forceinline__ void wait_cnt(int t) {
    if (ld_acquire(&g_cnt[t]) >= NT_PER_T) return;
    for (;;) {
        if (ld_acquire(&g_cnt[t]) >= NT_PER_T) return;
        __nanosleep(64);
    }
}

// fast activations via MUFU.TANH (validated: rel_err ~1e-7 in R10-R12)
__device__ __forceinline__ float tanh_fast(float x) {
    float r;
    asm("tanh.approx.f32 %0, %1;" : "=f"(r) : "f"(x));
    return r;
}
__device__ __forceinline__ float sig_fast(float x) {
    return fmaf(tanh_fast(0.5f * x), 0.5f, 0.5f);
}

__global__ void reset_kernel() {
    g_cnt[threadIdx.x] = 0;
}

__global__ __launch_bounds__(256, 3) void fused_kernel(
    const float* __restrict__ x,      // [T,B,300]
    const float* __restrict__ Wih0,   // [8,300]
    const float* __restrict__ bih0,
    const float* __restrict__ bhh0,
    const float* __restrict__ h0in,   // [2,B,2]
    const float* __restrict__ c0in,
    const float* __restrict__ Whh0,   // [8,2]
    const float* __restrict__ Wih1,   // [8,2]
    const float* __restrict__ Whh1,   // [8,2]
    const float* __restrict__ bih1,
    const float* __restrict__ bhh1,
    const float* __restrict__ Wlin,   // [1,2]
    const float* __restrict__ blin,
    float* __restrict__ out)          // [B]
{
    __shared__ float sWp[WP_FLOATS];  // producer: padded W
    __shared__ float sB[H4];
    __shared__ float sCW[4 * 16];     // consumer: A0,A1,C0,C1 by [kind][layer*8+g]

    const int bid = blockIdx.x;
    const int tid = threadIdx.x;

    if (bid >= NCONS) {
        // ============ PRODUCER (R8 lane-remap tile GEMM, proven) =============
        const int pid = bid - NCONS;
        const int t   = pid >> 4;
        const int s   = pid & 15;
        const int r0  = s * TROWS;
        const int nrows = (BB - r0 < TROWS) ? (BB - r0) : TROWS;   // 64 or 40

        for (int i = tid; i < 75 * 32; i += 256) {
            int d4  = i >> 5;
            int rem = i & 31;
            int j   = rem >> 3, g = rem & 7;
            sWp[d4 * WSLOT + j * 8 + g] = Wih0[g * DD + d4 * 4 + j];
        }
        if (tid < H4) sB[tid] = bih0[tid] + bhh0[tid];
        __syncthreads();

        const int lane = tid & 31;
        const int warp = tid >> 5;
        const int rloc = warp * 8 + (lane >> 2);   // 0..63
        const int c    = lane & 3;
        const bool rvalid = (rloc < nrows);
        const int row  = t * BB + r0 + rloc;

        const float4* xrow = reinterpret_cast<const float4*>(x + (size_t)row * DD);

        unsigned long long a0 = 0, a1 = 0, a2 = 0, a3 = 0;

        #pragma unroll
        for (int i = 0; i < 19; i++) {
            const int d4 = i * 4 + c;
            if (rvalid && d4 < 75) {
                float4 v = xrow[d4];
                const float* wb = &sWp[d4 * WSLOT];
                #pragma unroll
                for (int j = 0; j < 4; j++) {
                    const float xs = (j == 0) ? v.x : (j == 1) ? v.y : (j == 2) ? v.z : v.w;
                    unsigned long long xp = pack2(xs);
                    ulonglong2 wA = *reinterpret_cast<const ulonglong2*>(wb + j * 8);
                    ulonglong2 wB = *reinterpret_cast<const ulonglong2*>(wb + j * 8 + 4);
                    fma2(a0, xp, wA.x);
                    fma2(a1, xp, wA.y);
                    fma2(a2, xp, wB.x);
                    fma2(a3, xp, wB.y);
                }
            }
        }

        // reduce across the 4 col-group lanes of each row
        a0 = add2(a0, __shfl_xor_sync(0xffffffffu, a0, 1));
        a1 = add2(a1, __shfl_xor_sync(0xffffffffu, a1, 1));
        a2 = add2(a2, __shfl_xor_sync(0xffffffffu, a2, 1));
        a3 = add2(a3, __shfl_xor_sync(0xffffffffu, a3, 1));
        a0 = add2(a0, __shfl_xor_sync(0xffffffffu, a0, 2));
        a1 = add2(a1, __shfl_xor_sync(0xffffffffu, a1, 2));
        a2 = add2(a2, __shfl_xor_sync(0xffffffffu, a2, 2));
        a3 = add2(a3, __shfl_xor_sync(0xffffffffu, a3, 2));

        if (rvalid && c == 0) {
            ulonglong2 b01 = *reinterpret_cast<const ulonglong2*>(&sB[0]);
            ulonglong2 b23 = *reinterpret_cast<const ulonglong2*>(&sB[4]);
            a0 = add2(a0, b01.x);
            a1 = add2(a1, b01.y);
            a2 = add2(a2, b23.x);
            a3 = add2(a3, b23.y);
            float4 o0, o1;
            unpack2(a0, o0.x, o0.y);
            unpack2(a1, o0.z, o0.w);
            unpack2(a2, o1.x, o1.y);
            unpack2(a3, o1.z, o1.w);
            float4* dst = reinterpret_cast<float4*>(&g_xg[(size_t)row * H4]);
            dst[0] = o0;
            dst[1] = o1;
        }
        __threadfence();
        __syncthreads();
        if (tid == 0) atomicAdd(&g_cnt[t], 1);
        return;
    }

    // ============ CONSUMER (R12 ring consumer, weights in smem) ==============
    if (tid < 16) {
        const int l = tid >> 3, g = tid & 7;
        sCW[0 * 16 + tid] = l ? __ldg(&Whh1[g * 2 + 0]) : __ldg(&Whh0[g * 2 + 0]);
        sCW[1 * 16 + tid] = l ? __ldg(&Whh1[g * 2 + 1]) : __ldg(&Whh0[g * 2 + 1]);
        sCW[2 * 16 + tid] = l ? __ldg(&Wih1[g * 2 + 0]) : 0.0f;
        sCW[3 * 16 + tid] = l ? __ldg(&Wih1[g * 2 + 1]) : 0.0f;
    }
    __syncthreads();
    volatile const float* vw = sCW;

    const int warp = tid >> 5;
    const int lane = tid & 31;
    const bool l1  = (lane >= 16);
    const int wb   = l1 ? 8 : 0;
    const int e    = (bid * 8 + warp) * 16 + (lane & 15);   // 0..1023
    const int b    = (e < BB) ? e : (BB - 1);

    float ha, hb, ca, cb;
    float hpa = 0.0f, hpb = 0.0f;
    float vb[H4];   // l0: per-step xg; l1: constant bias

    if (!l1) {
        #pragma unroll
        for (int g = 0; g < H4; g++) vb[g] = 0.0f;
        ha = h0in[b * 2 + 0]; hb = h0in[b * 2 + 1];
        ca = c0in[b * 2 + 0]; cb = c0in[b * 2 + 1];
    } else {
        #pragma unroll
        for (int g = 0; g < H4; g++) vb[g] = __ldg(&bih1[g]) + __ldg(&bhh1[g]);
        ha = h0in[BB * 2 + b * 2 + 0]; hb = h0in[BB * 2 + b * 2 + 1];
        ca = c0in[BB * 2 + b * 2 + 0]; cb = c0in[BB * 2 + b * 2 + 1];
    }
    const float wl0 = __ldg(&Wlin[0]), wl1 = __ldg(&Wlin[1]), bl = __ldg(&blin[0]);

    const float4* xg4 = reinterpret_cast<const float4*>(g_xg);
    const int idx0 = b * 2;
    const int ST   = BB * 2;   // float4 stride per timestep

    // ---- prefetch ring: slots for steps s..s+3 (flag-gated) ----
    float4 r0[4], r1[4];
    #pragma unroll
    for (int d = 0; d < 4; d++) {
        wait_cnt(d);
        if (!l1) {
            r0[d] = __ldg(&xg4[idx0 + d * ST]);
            r1[d] = __ldg(&xg4[idx0 + d * ST + 1]);
        }
    }

    #pragma unroll 1
    for (int s4 = 0; s4 < TT / 4; s4++) {
        #pragma unroll
        for (int u = 0; u < 4; u++) {
            const int s = s4 * 4 + u;

            if (!l1) {
                vb[0] = r0[u].x; vb[1] = r0[u].y; vb[2] = r0[u].z; vb[3] = r0[u].w;
                vb[4] = r1[u].x; vb[5] = r1[u].y; vb[6] = r1[u].z; vb[7] = r1[u].w;
            }
            if (s + 4 < TT) {
                wait_cnt(s + 4);
                if (!l1) {
                    r0[u] = __ldg(&xg4[idx0 + (s + 4) * ST]);
                    r1[u] = __ldg(&xg4[idx0 + (s + 4) * ST + 1]);
                }
            }

            float pre[H4];
            #pragma unroll
            for (int g = 0; g < H4; g++) {
                float base = fmaf(vw[2 * 16 + wb + g], hpa,
                             fmaf(vw[3 * 16 + wb + g], hpb, vb[g]));
                pre[g] = fmaf(vw[0 * 16 + wb + g], ha,
                         fmaf(vw[1 * 16 + wb + g], hb, base));
            }

            float i0 = sig_fast(pre[0]),  i1 = sig_fast(pre[1]);
            float f0 = sig_fast(pre[2]),  f1 = sig_fast(pre[3]);
            float g0 = tanh_fast(pre[4]), g1 = tanh_fast(pre[5]);
            float o0 = sig_fast(pre[6]),  o1 = sig_fast(pre[7]);
            float nca = fmaf(f0, ca, i0 * g0);
            float ncb = fmaf(f1, cb, i1 * g1);
            float nha = o0 * tanh_fast(nca);
            float nhb = o1 * tanh_fast(ncb);

            const bool valid = l1 ? (s >= 1) : true;
            if (valid) { ca = nca; cb = ncb; ha = nha; hb = nhb; }

            hpa = __shfl_up_sync(0xffffffffu, ha, 16);
            hpb = __shfl_up_sync(0xffffffffu, hb, 16);
        }
    }

    // epilogue step s = TT: layer-1 lanes process t = TT-1 (vb == bias for l1)
    {
        float pre[H4];
        #pragma unroll
        for (int g = 0; g < H4; g++) {
            float base = fmaf(vw[2 * 16 + wb + g], hpa,
                         fmaf(vw[3 * 16 + wb + g], hpb, vb[g]));
            pre[g] = fmaf(vw[0 * 16 + wb + g], ha,
                     fmaf(vw[1 * 16 + wb + g], hb, base));
        }
        float i0 = sig_fast(pre[0]),  i1 = sig_fast(pre[1]);
        float f0 = sig_fast(pre[2]),  f1 = sig_fast(pre[3]);
        float g0 = tanh_fast(pre[4]), g1 = tanh_fast(pre[5]);
        float o0 = sig_fast(pre[6]),  o1 = sig_fast(pre[7]);
        float nca = fmaf(f0, ca, i0 * g0);
        float ncb = fmaf(f1, cb, i1 * g1);
        float nha = o0 * tanh_fast(nca);
        float nhb = o1 * tanh_fast(ncb);
        if (l1) { ca = nca; cb = ncb; ha = nha; hb = nhb; }
    }

    if (l1 && e < BB)
        out[b] = fmaf(wl0, ha, fmaf(wl1, hb, bl));
}

// ---------------------------------------------------------------------------
extern "C" void kernel_launch(void* const* d_in, const int* in_sizes, int n_in,
                              void* d_out, int out_size)
{
    const float* x     = (const float*)d_in[0];
    const float* h0    = (const float*)d_in[1];
    const float* c0    = (const float*)d_in[2];
    const float* Wih0  = (const float*)d_in[3];
    const float* Whh0  = (const float*)d_in[4];
    const float* bih0  = (const float*)d_in[5];
    const float* bhh0  = (const float*)d_in[6];
    const float* Wih1  = (const float*)d_in[7];
    const float* Whh1  = (const float*)d_in[8];
    const float* bih1  = (const float*)d_in[9];
    const float* bhh1  = (const float*)d_in[10];
    const float* Wlin  = (const float*)d_in[11];
    const float* blin  = (const float*)d_in[12];
    float* out = (float*)d_out;

    reset_kernel<<<1, TT>>>();
    fused_kernel<<<NCONS + NPROD, 256>>>(
        x, Wih0, bih0, bhh0,
        h0, c0, Whh0, Wih1, Whh1, bih1, bhh1, Wlin, blin,
        out);
}